// round 12
// baseline (speedup 1.0000x reference)
#include <cuda_runtime.h>
#include <cuda_fp16.h>
#include <math.h>

// Levels: RES = {128, 256, 512, 1024}, C=4 channels, 3 planes per level.
//
// Hybrid table, all lc-prefolded, zero-bordered, fp16:
//  - Levels 0-2: "quad table"  Quad[y][s] (32B) = 2x2 corner texels
//      -> one bilinear sample = 2 LDG.128 in the SAME 32B sector.
//  - Level 3:    "pair table"  P[ye][s] (16B) = x-adjacent texel pair
//      -> one sample = 2 LDG.128, rows rp apart (2 sectors, but L2-resident).
// Total ~84MB -> fits L2 (126MB). Output uses __stcs so the 201MB write
// stream doesn't evict the tables.
#define NLEV 4

// quads: 3*(R+1)^2 for R=128,256,512 -> 49923+198147+789507 = 1037577 quads
__device__ __align__(32) uint4 g_quads[2075154];    // 2 uint4 per quad (~33MB)
// pairs (level 3): 3*(R+2)*(R+1) = 3*1026*1025 = 3154950 (~50MB)
__device__ __align__(16) uint4 g_pairs3[3154950];
__device__ __align__(16) float g_linec[48];         // [l][p][c]

__constant__ int c_qlvloff[3] = {0, 49923, 248070};
// qbase[l*3+p] = qlvloff[l] + p*(R+1)^2
__constant__ int c_qbase[9] = {
    0,      16641,  33282,
    49923,  115972, 182021,
    248070, 511239, 774408};
__constant__ int   c_qrp[3] = {129, 257, 513};
__constant__ float c_qhR[3] = {64.f, 128.f, 256.f};
// level-3 pair table: pbase[p] = p*(R+2)*(R+1)
__constant__ int c_pbase[3] = {0, 1051650, 2103300};

// bit-reinterpret helpers (no-op in SASS)
__device__ __forceinline__ unsigned int h2_as_u32(__half2 h) {
    return *reinterpret_cast<unsigned int*>(&h);
}
__device__ __forceinline__ __half2 u32_as_h2(unsigned int u) {
    return *reinterpret_cast<__half2*>(&u);
}

// ---------------------------------------------------------------------------
// Line constants: triline grid_sample degenerates to
//   linec[l,p,c] = 0.5*(tl[p,c,R/2-1,0] + tl[p,c,R/2,0])
// Runs BEFORE the table builders, which fold these into the texels.
// ---------------------------------------------------------------------------
__global__ void linec_kernel(const float* __restrict__ t0, const float* __restrict__ t1,
                             const float* __restrict__ t2, const float* __restrict__ t3) {
    int i = threadIdx.x;
    if (i >= 48) return;
    const int res[NLEV] = {128, 256, 512, 1024};
    int l  = i / 12;
    int pc = i % 12;            // p*4 + c
    const float* t = (l == 0) ? t0 : (l == 1) ? t1 : (l == 2) ? t2 : t3;
    int r = res[l];
    g_linec[i] = 0.5f * (t[pc * r + r / 2 - 1] + t[pc * r + r / 2]);
}

// ---------------------------------------------------------------------------
// Build fp16 quad table (levels 0-2), zero borders, lc-prefolded.
// grid: ( ceil((R+1)/128), R+1, 3 )
// ---------------------------------------------------------------------------
__global__ void quad_kernel(const float* __restrict__ in, int R, int lvl) {
    int s = blockIdx.x * blockDim.x + threadIdx.x;       // 0..R
    if (s > R) return;
    int y = blockIdx.y;                                  // 0..R
    int p = blockIdx.z;
    int rr = R * R;
    const float* bp = in + (size_t)(p * 4) * rr;
    const float* lc = g_linec + lvl * 12 + p * 4;

    int ylo = y - 1, yhi = y;
    int xlo = s - 1, xhi = s;
    bool ylok = (ylo >= 0);
    bool yhok = (yhi < R);
    bool xlok = (xlo >= 0);
    bool xhok = (xhi < R);

    __half hv[16];
#pragma unroll
    for (int c = 0; c < 4; c++) {
        const float* cp = bp + (size_t)c * rr;
        float l_ = lc[c];
        float v00 = (ylok && xlok) ? __ldg(cp + ylo * R + xlo) * l_ : 0.f;
        float v01 = (ylok && xhok) ? __ldg(cp + ylo * R + xhi) * l_ : 0.f;
        float v10 = (yhok && xlok) ? __ldg(cp + yhi * R + xlo) * l_ : 0.f;
        float v11 = (yhok && xhok) ? __ldg(cp + yhi * R + xhi) * l_ : 0.f;
        hv[c]      = __float2half_rn(v00);
        hv[4 + c]  = __float2half_rn(v01);
        hv[8 + c]  = __float2half_rn(v10);
        hv[12 + c] = __float2half_rn(v11);
    }
    uint4 t0, t1;
    t0.x = h2_as_u32(__halves2half2(hv[0],  hv[1]));   // y0,x0 c0,c1
    t0.y = h2_as_u32(__halves2half2(hv[2],  hv[3]));
    t0.z = h2_as_u32(__halves2half2(hv[4],  hv[5]));   // y0,x1
    t0.w = h2_as_u32(__halves2half2(hv[6],  hv[7]));
    t1.x = h2_as_u32(__halves2half2(hv[8],  hv[9]));   // y1,x0
    t1.y = h2_as_u32(__halves2half2(hv[10], hv[11]));
    t1.z = h2_as_u32(__halves2half2(hv[12], hv[13]));  // y1,x1
    t1.w = h2_as_u32(__halves2half2(hv[14], hv[15]));

    int rp = R + 1;
    int qidx = c_qlvloff[lvl] + p * rp * rp + y * rp + s;
    g_quads[2 * qidx]     = t0;
    g_quads[2 * qidx + 1] = t1;
}

// ---------------------------------------------------------------------------
// Build fp16 pair table (level 3, R=1024), zero borders, lc-prefolded.
// grid: ( ceil((R+1)/256), R+2, 3 )
// ---------------------------------------------------------------------------
__global__ void pair_kernel(const float* __restrict__ in, int R) {
    int s  = blockIdx.x * blockDim.x + threadIdx.x;      // 0..R
    if (s > R) return;
    int ye = blockIdx.y;                                 // 0..R+1
    int p  = blockIdx.z;
    int y  = ye - 1;
    int rr = R * R;
    bool yok = (y >= 0) && (y < R);
    bool lok = yok && (s >= 1);
    bool hok = yok && (s < R);
    const float* bp = in + (size_t)(p * 4) * rr + (size_t)y * R;
    const float* lc = g_linec + 3 * 12 + p * 4;          // level 3

    __half h[8];
#pragma unroll
    for (int c = 0; c < 4; c++) {
        float l_ = lc[c];
        float lv = lok ? __ldg(bp + (size_t)c * rr + (s - 1)) * l_ : 0.f;
        float hv = hok ? __ldg(bp + (size_t)c * rr + s)       * l_ : 0.f;
        h[c]     = __float2half_rn(lv);
        h[4 + c] = __float2half_rn(hv);
    }
    uint4 t;
    t.x = h2_as_u32(__halves2half2(h[0], h[1]));
    t.y = h2_as_u32(__halves2half2(h[2], h[3]));
    t.z = h2_as_u32(__halves2half2(h[4], h[5]));
    t.w = h2_as_u32(__halves2half2(h[6], h[7]));
    int rp = R + 1;
    g_pairs3[p * (R + 2) * rp + ye * rp + s] = t;
}

// ---------------------------------------------------------------------------
// Shared bilinear finish: t0 = row y0 {x0 texel, x1 texel}, t1 = row y1.
// ---------------------------------------------------------------------------
__device__ __forceinline__ float4 lerp_finish(uint4 t0, uint4 t1, float wx, float wy) {
    __half2 wx2 = __float2half2_rn(wx);
    __half2 wy2 = __float2half2_rn(wy);
    __half2 a01 = u32_as_h2(t0.x), a23 = u32_as_h2(t0.y);   // y0,x0
    __half2 b01 = u32_as_h2(t0.z), b23 = u32_as_h2(t0.w);   // y0,x1
    __half2 c01 = u32_as_h2(t1.x), c23 = u32_as_h2(t1.y);   // y1,x0
    __half2 d01 = u32_as_h2(t1.z), d23 = u32_as_h2(t1.w);   // y1,x1
    __half2 r01 = __hfma2(__hsub2(b01, a01), wx2, a01);
    __half2 r23 = __hfma2(__hsub2(b23, a23), wx2, a23);
    __half2 s01 = __hfma2(__hsub2(d01, c01), wx2, c01);
    __half2 s23 = __hfma2(__hsub2(d23, c23), wx2, c23);
    __half2 v01 = __hfma2(__hsub2(s01, r01), wy2, r01);
    __half2 v23 = __hfma2(__hsub2(s23, r23), wy2, r23);
    float2 f01 = __half22float2(v01);
    float2 f23 = __half22float2(v23);
    return make_float4(f01.x, f01.y, f23.x, f23.y);
}

// ---------------------------------------------------------------------------
// Main kernel: 4 threads per point, assigned BY WARP:
//   warp w handles level (w & 3) for points [(w>>2)*32, (w>>2)*32+32).
// The quad/pair branch is warp-uniform -> no divergence.
// ---------------------------------------------------------------------------
__global__ __launch_bounds__(256)
void enc_kernel(const float* __restrict__ x, float* __restrict__ out, int N) {
    int tid  = blockIdx.x * blockDim.x + threadIdx.x;
    int lane = tid & 31;
    int w    = tid >> 5;
    int l    = w & 3;
    int point = ((w >> 2) << 5) + lane;
    if (point >= N) return;

    const float* xp = x + 3 * (size_t)point;
    float px = fmaf(2.f, __ldg(xp + 0), -1.f);
    float py = fmaf(2.f, __ldg(xp + 1), -1.f);
    float pz = fmaf(2.f, __ldg(xp + 2), -1.f);

    // plane p: (u=width, v=height) per projections (xz), (yx), (zy)
    float uu[3] = {px, py, pz};
    float vv[3] = {pz, px, py};
    float wl[3] = {fmaf(-0.5f, fabsf(px), 1.f),
                   fmaf(-0.5f, fabsf(py), 1.f),
                   fmaf(-0.5f, fabsf(pz), 1.f)};

    float4* o4 = reinterpret_cast<float4*>(out) + (size_t)point * 12 + l * 3;

    if (l < 3) {
        // quad path (levels 0-2)
        float hR = c_qhR[l];
        int   rp = c_qrp[l];
#pragma unroll
        for (int p = 0; p < 3; p++) {
            float fx = fmaf(uu[p], hR, hR - 0.5f);
            float fy = fmaf(vv[p], hR, hR - 0.5f);
            float fx0 = floorf(fx), fy0 = floorf(fy);
            float wx = fx - fx0,   wy = fy - fy0;
            int ix = (int)fx0, iy = (int)fy0;
            int qidx = c_qbase[l * 3 + p] + (iy + 1) * rp + (ix + 1);
            uint4 t0 = __ldg(&g_quads[2 * qidx]);
            uint4 t1 = __ldg(&g_quads[2 * qidx + 1]);
            float4 f = lerp_finish(t0, t1, wx, wy);
            float s = wl[p];
            float4 r = make_float4(f.x * s, f.y * s, f.z * s, f.w * s);
            __stcs(&o4[p], r);
        }
    } else {
        // pair path (level 3, R=1024)
        const float hR = 512.f;
        const int   rp = 1025;
#pragma unroll
        for (int p = 0; p < 3; p++) {
            float fx = fmaf(uu[p], hR, hR - 0.5f);
            float fy = fmaf(vv[p], hR, hR - 0.5f);
            float fx0 = floorf(fx), fy0 = floorf(fy);
            float wx = fx - fx0,   wy = fy - fy0;
            int ix = (int)fx0, iy = (int)fy0;
            int idx = c_pbase[p] + (iy + 1) * rp + (ix + 1);
            uint4 t0 = __ldg(&g_pairs3[idx]);
            uint4 t1 = __ldg(&g_pairs3[idx + rp]);
            float4 f = lerp_finish(t0, t1, wx, wy);
            float s = wl[p];
            float4 r = make_float4(f.x * s, f.y * s, f.z * s, f.w * s);
            __stcs(&o4[p], r);
        }
    }
}

// ---------------------------------------------------------------------------
// Launch: identify inputs by size (robust to metadata ordering)
// ---------------------------------------------------------------------------
extern "C" void kernel_launch(void* const* d_in, const int* in_sizes, int n_in,
                              void* d_out, int out_size) {
    const int res[NLEV] = {128, 256, 512, 1024};

    // triplane_l : 12*R*R = 196608, 786432, 3145728, 12582912
    // triline_l  : 12*R   = 1536, 3072, 6144, 12288
    // x          : 3*N    = 3145728 (ambiguous with triplane_2)
    int tp_idx[NLEV] = {-1, -1, -1, -1};
    int tl_idx[NLEV] = {-1, -1, -1, -1};
    int amb[2]; int n_amb = 0;
    int x_idx = -1;

    for (int i = 0; i < n_in; i++) {
        int s = in_sizes[i];
        if      (s == 196608)   tp_idx[0] = i;
        else if (s == 786432)   tp_idx[1] = i;
        else if (s == 12582912) tp_idx[3] = i;
        else if (s == 1536)     tl_idx[0] = i;
        else if (s == 3072)     tl_idx[1] = i;
        else if (s == 6144)     tl_idx[2] = i;
        else if (s == 12288)    tl_idx[3] = i;
        else if (s == 3145728)  { if (n_amb < 2) amb[n_amb++] = i; }
        else if (x_idx < 0)     x_idx = i;
    }
    if (n_amb == 1) {
        tp_idx[2] = amb[0];
    } else if (n_amb == 2) {
        // triplane_0..3 occupy contiguous ascending indices in either ordering
        int a = amb[0], b = amb[1];
        if (a > tp_idx[1] && a < tp_idx[3]) { tp_idx[2] = a; x_idx = b; }
        else                                { tp_idx[2] = b; x_idx = a; }
    }
    if (x_idx < 0) x_idx = 0;

    const float* x = (const float*)d_in[x_idx];
    int N = in_sizes[x_idx] / 3;

    // 1) line constants first (folded into tables)
    linec_kernel<<<1, 64>>>((const float*)d_in[tl_idx[0]], (const float*)d_in[tl_idx[1]],
                            (const float*)d_in[tl_idx[2]], (const float*)d_in[tl_idx[3]]);

    // 2) quad tables for levels 0-2
    for (int l = 0; l < 3; l++) {
        const float* tp = (const float*)d_in[tp_idx[l]];
        int R = res[l];
        dim3 grid((R + 1 + 127) / 128, R + 1, 3);
        quad_kernel<<<grid, 128>>>(tp, R, l);
    }
    // 3) pair table for level 3
    {
        const float* tp = (const float*)d_in[tp_idx[3]];
        int R = res[3];
        dim3 grid((R + 1 + 255) / 256, R + 2, 3);
        pair_kernel<<<grid, 256>>>(tp, R);
    }

    // 4) main pass: 4 threads per point, level assigned per warp
    long long threads = 4LL * N;
    enc_kernel<<<(int)((threads + 255) / 256), 256>>>(x, (float*)d_out, N);
}

// round 13
// speedup vs baseline: 1.1292x; 1.1292x over previous
#include <cuda_runtime.h>
#include <cuda_fp16.h>
#include <math.h>

// Levels: RES = {128, 256, 512, 1024}, C=4 channels, 3 planes per level.
//
// Plane storage: fp16 "quad table" per (level, plane), lc-prefolded, zero-
// bordered:  Quad[y][s] (32B, 32B-aligned) = 2x2 corner texels
//   { t(y-1,s-1), t(y-1,s), t(y,s-1), t(y,s) }, each texel 4ch fp16 = 8B.
// One bilinear sample at (ix,iy) reads Quad[iy+1][ix+1] = 2 LDG.128 in the
// SAME 32B sector. enc uses 8 threads/point (pair-lane row split) for best
// load/store coalescing (R10 = best measured config).
#define NLEV 4

// quads per level: 3*(R+1)^2 -> 49923,198147,789507,3151875 ; total 4189452 (~134MB)
__device__ __align__(32) uint4 g_quads[8378904];   // 2 uint4 per quad
__device__ __align__(16) float g_linec[48];        // [l][p][c]

__constant__ int   c_res[NLEV]  = {128, 256, 512, 1024};
__constant__ int   c_qlvl[NLEV] = {0, 49923, 248070, 1037577};

// per-sample (s = l*3+p) prefolded params: qbase = qlvl[l] + p*(R+1)^2
__constant__ int c_sbase[12] = {
    0,       16641,   33282,
    49923,   115972,  182021,
    248070,  511239,  774408,
    1037577, 2088202, 3138827};
__constant__ int   c_srp[12] = {129,129,129, 257,257,257, 513,513,513, 1025,1025,1025};
__constant__ float c_shR[12] = {64.f,64.f,64.f, 128.f,128.f,128.f,
                                256.f,256.f,256.f, 512.f,512.f,512.f};
__constant__ int c_spn[12] = {0,1,2, 0,1,2, 0,1,2, 0,1,2};

// bit-reinterpret helpers (no-op in SASS)
__device__ __forceinline__ unsigned int h2_as_u32(__half2 h) {
    return *reinterpret_cast<unsigned int*>(&h);
}
__device__ __forceinline__ __half2 u32_as_h2(unsigned int u) {
    return *reinterpret_cast<__half2*>(&u);
}

// ---------------------------------------------------------------------------
// Line constants: triline grid_sample degenerates to
//   linec[l,p,c] = 0.5*(tl[p,c,R/2-1,0] + tl[p,c,R/2,0])
// Runs BEFORE the quad builders, which fold these into the texels.
// ---------------------------------------------------------------------------
__global__ void linec_kernel(const float* __restrict__ t0, const float* __restrict__ t1,
                             const float* __restrict__ t2, const float* __restrict__ t3) {
    int i = threadIdx.x;
    if (i >= 48) return;
    int l  = i / 12;
    int pc = i % 12;            // p*4 + c
    const float* t = (l == 0) ? t0 : (l == 1) ? t1 : (l == 2) ? t2 : t3;
    int r = c_res[l];
    g_linec[i] = 0.5f * (t[pc * r + r / 2 - 1] + t[pc * r + r / 2]);
}

// ---------------------------------------------------------------------------
// Vectorized quad builder: each thread builds 4 consecutive quads (s0..s0+3).
// Per (channel,row): one predicated scalar (x=s0-1) + one aligned float4
// (x=s0..s0+3). Since R % 4 == 0, either the full float4 is in-range
// (s0+4 <= R) or s0 == R (single border quad, no float4 needed).
// grid: (ceil((R/4+1)/128), R+1, 3*levels_in_launch) ; lvl = lvl0 + z/3, p = z%3
// ---------------------------------------------------------------------------
__global__ __launch_bounds__(128)
void quadv_kernel(const float* __restrict__ inA, const float* __restrict__ inB,
                  const float* __restrict__ inC, int lvl0) {
    int zi  = blockIdx.z;
    int li  = zi / 3;                       // level index within launch (0..2)
    int lvl = lvl0 + li;
    int p   = zi % 3;
    int R   = c_res[lvl];
    int y   = blockIdx.y;
    if (y > R) return;
    int s0 = (blockIdx.x * blockDim.x + threadIdx.x) * 4;
    if (s0 > R) return;
    const float* in = (li == 0) ? inA : (li == 1) ? inB : inC;

    int rr = R * R;
    const float* bp = in + (size_t)(p * 4) * rr;
    const float* lc = g_linec + lvl * 12 + p * 4;

    int ylo = y - 1, yhi = y;
    bool ylov  = (ylo >= 0);
    bool yhiv  = (yhi < R);
    bool fullv = (s0 + 4 <= R);             // float4 fully in-range
    bool m1v   = (s0 >= 1);                 // scalar x = s0-1 in-range

    // 5-value x-windows per channel per row: w[0]=x(s0-1), w[1..4]=x(s0..s0+3)
    float wlo[4][5], whi[4][5];
#pragma unroll
    for (int c = 0; c < 4; c++) {
        float l_ = lc[c];
        const float* rl = bp + (size_t)c * rr + (size_t)ylo * R;
        const float* rh = bp + (size_t)c * rr + (size_t)yhi * R;
        float  m1l = (ylov && m1v) ? __ldg(rl + s0 - 1) : 0.f;
        float  m1h = (yhiv && m1v) ? __ldg(rh + s0 - 1) : 0.f;
        float4 vl = make_float4(0.f, 0.f, 0.f, 0.f);
        float4 vh = make_float4(0.f, 0.f, 0.f, 0.f);
        if (ylov && fullv) vl = __ldg(reinterpret_cast<const float4*>(rl + s0));
        if (yhiv && fullv) vh = __ldg(reinterpret_cast<const float4*>(rh + s0));
        wlo[c][0] = m1l * l_; wlo[c][1] = vl.x * l_; wlo[c][2] = vl.y * l_;
        wlo[c][3] = vl.z * l_; wlo[c][4] = vl.w * l_;
        whi[c][0] = m1h * l_; whi[c][1] = vh.x * l_; whi[c][2] = vh.y * l_;
        whi[c][3] = vh.z * l_; whi[c][4] = vh.w * l_;
    }

    int rp = R + 1;
    int qbase = c_qlvl[lvl] + p * rp * rp + y * rp + s0;
#pragma unroll
    for (int j = 0; j < 4; j++) {
        if (s0 + j > R) break;
        uint4 t0, t1;
        // row y0 (= input row y-1): x0 texel (w[j]), x1 texel (w[j+1])
        t0.x = h2_as_u32(__halves2half2(__float2half_rn(wlo[0][j]),     __float2half_rn(wlo[1][j])));
        t0.y = h2_as_u32(__halves2half2(__float2half_rn(wlo[2][j]),     __float2half_rn(wlo[3][j])));
        t0.z = h2_as_u32(__halves2half2(__float2half_rn(wlo[0][j + 1]), __float2half_rn(wlo[1][j + 1])));
        t0.w = h2_as_u32(__halves2half2(__float2half_rn(wlo[2][j + 1]), __float2half_rn(wlo[3][j + 1])));
        // row y1 (= input row y)
        t1.x = h2_as_u32(__halves2half2(__float2half_rn(whi[0][j]),     __float2half_rn(whi[1][j])));
        t1.y = h2_as_u32(__halves2half2(__float2half_rn(whi[2][j]),     __float2half_rn(whi[3][j])));
        t1.z = h2_as_u32(__halves2half2(__float2half_rn(whi[0][j + 1]), __float2half_rn(whi[1][j + 1])));
        t1.w = h2_as_u32(__halves2half2(__float2half_rn(whi[2][j + 1]), __float2half_rn(whi[3][j + 1])));
        g_quads[2 * (qbase + j)]     = t0;
        g_quads[2 * (qbase + j) + 1] = t1;
    }
}

// ---------------------------------------------------------------------------
// Main kernel: 8 threads per point. Pair (2j, 2j+1) handles sample s = j+4r
// per round r=0..2; even lane loads quad row y0, odd lane row y1. After the
// per-row x-lerp, rows are exchanged via shfl_xor(1); the even lane finalizes
// channels 0-1 and the odd lane channels 2-3 (8B streaming store each).
// ---------------------------------------------------------------------------
__global__ __launch_bounds__(256)
void enc_kernel(const float* __restrict__ x, float* __restrict__ out, int N) {
    int tid   = blockIdx.x * blockDim.x + threadIdx.x;
    int point = tid >> 3;
    bool live = (point < N);
    if (point >= N) point = N - 1;     // clamp: keep all lanes active for shfl
    int t   = tid & 7;
    int j   = t >> 1;                  // pair id 0..3
    int row = t & 1;                   // 0 = row y0, 1 = row y1

    const float* xp = x + 3 * (size_t)point;
    float px = fmaf(2.f, __ldg(xp + 0), -1.f);
    float py = fmaf(2.f, __ldg(xp + 1), -1.f);
    float pz = fmaf(2.f, __ldg(xp + 2), -1.f);

    float2* o2 = reinterpret_cast<float2*>(out + (size_t)point * 48);

#pragma unroll
    for (int r = 0; r < 3; r++) {
        int s = j + 4 * r;             // sample id 0..11

        int   base = c_sbase[s];
        int   rp   = c_srp[s];
        float hR   = c_shR[s];
        int   p    = c_spn[s];

        // plane p: (u=width, v=height) per projections (xz), (yx), (zy)
        float u  = (p == 0) ? px : (p == 1) ? py : pz;
        float v  = (p == 0) ? pz : (p == 1) ? px : py;
        float wl = fmaf(-0.5f, fabsf(u), 1.f);   // line factor uses axis coord = u

        float fx = fmaf(u, hR, hR - 0.5f);
        float fy = fmaf(v, hR, hR - 0.5f);
        float fx0 = floorf(fx), fy0 = floorf(fy);
        float wx = fx - fx0,   wy = fy - fy0;
        int ix = (int)fx0, iy = (int)fy0;

        int qidx = base + (iy + 1) * rp + (ix + 1);
        uint4 tq = __ldg(&g_quads[2 * qidx + row]);   // my row: (x0 c01,c23),(x1 c01,c23)

        __half2 wx2 = __float2half2_rn(wx);
        __half2 a01 = u32_as_h2(tq.x), a23 = u32_as_h2(tq.y);   // x0
        __half2 b01 = u32_as_h2(tq.z), b23 = u32_as_h2(tq.w);   // x1

        // x-lerp my row
        __half2 r01 = __hfma2(__hsub2(b01, a01), wx2, a01);
        __half2 r23 = __hfma2(__hsub2(b23, a23), wx2, a23);

        // exchange with partner row
        unsigned o01 = __shfl_xor_sync(0xffffffffu, h2_as_u32(r01), 1);
        unsigned o23 = __shfl_xor_sync(0xffffffffu, h2_as_u32(r23), 1);

        // even lane (row 0): channels 0-1 -> lo = own r01 (y0), hi = partner (y1)
        // odd  lane (row 1): channels 2-3 -> lo = partner r23 (y0), hi = own (y1)
        __half2 lo = (row == 0) ? r01 : u32_as_h2(o23);
        __half2 hi = (row == 0) ? u32_as_h2(o01) : r23;

        __half2 wy2 = __float2half2_rn(wy);
        __half2 vv2 = __hfma2(__hsub2(hi, lo), wy2, lo);
        float2 f = __half22float2(vv2);

        float2 res;
        res.x = f.x * wl;
        res.y = f.y * wl;
        if (live) __stcs(&o2[s * 2 + row], res);
    }
}

// ---------------------------------------------------------------------------
// Launch: identify inputs by size (robust to metadata ordering)
// ---------------------------------------------------------------------------
extern "C" void kernel_launch(void* const* d_in, const int* in_sizes, int n_in,
                              void* d_out, int out_size) {
    // triplane_l : 12*R*R = 196608, 786432, 3145728, 12582912
    // triline_l  : 12*R   = 1536, 3072, 6144, 12288
    // x          : 3*N    = 3145728 (ambiguous with triplane_2)
    int tp_idx[NLEV] = {-1, -1, -1, -1};
    int tl_idx[NLEV] = {-1, -1, -1, -1};
    int amb[2]; int n_amb = 0;
    int x_idx = -1;

    for (int i = 0; i < n_in; i++) {
        int s = in_sizes[i];
        if      (s == 196608)   tp_idx[0] = i;
        else if (s == 786432)   tp_idx[1] = i;
        else if (s == 12582912) tp_idx[3] = i;
        else if (s == 1536)     tl_idx[0] = i;
        else if (s == 3072)     tl_idx[1] = i;
        else if (s == 6144)     tl_idx[2] = i;
        else if (s == 12288)    tl_idx[3] = i;
        else if (s == 3145728)  { if (n_amb < 2) amb[n_amb++] = i; }
        else if (x_idx < 0)     x_idx = i;
    }
    if (n_amb == 1) {
        tp_idx[2] = amb[0];
    } else if (n_amb == 2) {
        // triplane_0..3 occupy contiguous ascending indices in either ordering
        int a = amb[0], b = amb[1];
        if (a > tp_idx[1] && a < tp_idx[3]) { tp_idx[2] = a; x_idx = b; }
        else                                { tp_idx[2] = b; x_idx = a; }
    }
    if (x_idx < 0) x_idx = 0;

    const float* x = (const float*)d_in[x_idx];
    int N = in_sizes[x_idx] / 3;

    // Launch 1: line constants (folded into quad tables)
    linec_kernel<<<1, 64>>>((const float*)d_in[tl_idx[0]], (const float*)d_in[tl_idx[1]],
                            (const float*)d_in[tl_idx[2]], (const float*)d_in[tl_idx[3]]);

    // Launch 2: quad tables, levels 0-2 fused (R<=512: grid covers largest)
    {
        dim3 grid((512 / 4 + 1 + 127) / 128, 513, 9);   // (2, 513, 9)
        quadv_kernel<<<grid, 128>>>((const float*)d_in[tp_idx[0]],
                                    (const float*)d_in[tp_idx[1]],
                                    (const float*)d_in[tp_idx[2]], 0);
    }
    // Launch 3: quad table, level 3 (R=1024)
    {
        dim3 grid((1024 / 4 + 1 + 127) / 128, 1025, 3); // (3, 1025, 3)
        const float* t3 = (const float*)d_in[tp_idx[3]];
        quadv_kernel<<<grid, 128>>>(t3, t3, t3, 3);
    }

    // Launch 4: main pass (8 threads per point) -- lands on the ncu capture slot
    long long threads = 8LL * N;
    enc_kernel<<<(int)((threads + 255) / 256), 256>>>(x, (float*)d_out, N);
}